// round 10
// baseline (speedup 1.0000x reference)
#include <cuda_runtime.h>
#include <cuda_fp16.h>
#include <cstdint>

#define B_  2
#define S_  2048
#define U_  1024
#define H_  16
#define DK_ 64
#define BS_ (B_ * S_)

// persistent fp16 scratch (allocation-free rule: __device__ globals)
// A-operands: split hi/lo.  B-operands: single rounded fp16.
__device__ __half in_q_hi[BS_ * U_], in_q_lo[BS_ * U_];
__device__ __half in_k_hi[BS_ * U_], in_k_lo[BS_ * U_];
__device__ __half in_v_hi[BS_ * U_], in_v_lo[BS_ * U_];
__device__ __half w_q_s[U_ * U_], w_k_s[U_ * U_], w_v_s[U_ * U_], w_o_s[U_ * U_];
__device__ __half g_q_hi[BS_ * U_], g_q_lo[BS_ * U_];
__device__ __half g_k_s[BS_ * U_];
__device__ __half g_v_s[BS_ * U_];
__device__ __half g_att_hi[BS_ * U_], g_att_lo[BS_ * U_];

// ---------------------------------------------------------------------------
// helpers
// ---------------------------------------------------------------------------
__device__ __forceinline__ uint32_t smem_u32(const void* p) {
    uint32_t a;
    asm("{ .reg .u64 t; cvta.to.shared.u64 t, %1; cvt.u32.u64 %0, t; }" : "=r"(a) : "l"(p));
    return a;
}

#define LDSM_X4(r0, r1, r2, r3, addr)                                         \
    asm volatile("ldmatrix.sync.aligned.m8n8.x4.shared.b16 {%0,%1,%2,%3}, [%4];" \
        : "=r"(r0), "=r"(r1), "=r"(r2), "=r"(r3) : "r"(addr))

#define LDSM_X4_T(r0, r1, r2, r3, addr)                                       \
    asm volatile("ldmatrix.sync.aligned.m8n8.x4.trans.shared.b16 {%0,%1,%2,%3}, [%4];" \
        : "=r"(r0), "=r"(r1), "=r"(r2), "=r"(r3) : "r"(addr))

#define MMA_F16(d, a, b0, b1)                                                 \
    asm volatile("mma.sync.aligned.m16n8k16.row.col.f32.f16.f16.f32 "         \
        "{%0,%1,%2,%3},{%4,%5,%6,%7},{%8,%9},{%0,%1,%2,%3};"                  \
        : "+f"((d)[0]), "+f"((d)[1]), "+f"((d)[2]), "+f"((d)[3])              \
        : "r"((a)[0]), "r"((a)[1]), "r"((a)[2]), "r"((a)[3]), "r"(b0), "r"(b1))

#define CP_ASYNC16(saddr, gptr) \
    asm volatile("cp.async.cg.shared.global [%0], [%1], 16;" :: "r"(saddr), "l"(gptr) : "memory")
#define CP_COMMIT() asm volatile("cp.async.commit_group;" ::: "memory")
template <int N> __device__ __forceinline__ void cp_wait() {
    asm volatile("cp.async.wait_group %0;" :: "n"(N) : "memory");
}

__device__ __forceinline__ uint32_t pack_h2(__half a, __half b) {
    __half2 h = __halves2half2(a, b);
    return *reinterpret_cast<uint32_t*>(&h);
}

__device__ __forceinline__ void cvt_split_h(const float4& f, uint2& hi, uint2& lo) {
    __half h0 = __float2half_rn(f.x), h1 = __float2half_rn(f.y);
    __half h2 = __float2half_rn(f.z), h3 = __float2half_rn(f.w);
    __half l0 = __float2half_rn(f.x - __half2float(h0));
    __half l1 = __float2half_rn(f.y - __half2float(h1));
    __half l2 = __float2half_rn(f.z - __half2float(h2));
    __half l3 = __float2half_rn(f.w - __half2float(h3));
    hi.x = pack_h2(h0, h1); hi.y = pack_h2(h2, h3);
    lo.x = pack_h2(l0, l1); lo.y = pack_h2(l2, l3);
}

__device__ __forceinline__ void cvt_single_h(const float4& f, uint2& r) {
    r.x = pack_h2(__float2half_rn(f.x), __float2half_rn(f.y));
    r.y = pack_h2(__float2half_rn(f.z), __float2half_rn(f.w));
}

__device__ __forceinline__ void pack_split2h(float a, float b, uint32_t& hi, uint32_t& lo) {
    __half ha = __float2half_rn(a), hb = __float2half_rn(b);
    __half la = __float2half_rn(a - __half2float(ha));
    __half lb = __float2half_rn(b - __half2float(hb));
    hi = pack_h2(ha, hb); lo = pack_h2(la, lb);
}

// ---------------------------------------------------------------------------
// one-shot pre-pass: activations -> split hi/lo fp16; weights -> single fp16.
// ---------------------------------------------------------------------------
__global__ __launch_bounds__(256) void convert_all_kernel(
    const float* __restrict__ q, const float* __restrict__ k,
    const float* __restrict__ v, const float* __restrict__ wq,
    const float* __restrict__ wk, const float* __restrict__ wv,
    const float* __restrict__ wo,
    __half* __restrict__ qh, __half* __restrict__ ql,
    __half* __restrict__ kh, __half* __restrict__ kl,
    __half* __restrict__ vh, __half* __restrict__ vl,
    __half* __restrict__ wqs, __half* __restrict__ wks,
    __half* __restrict__ wvs, __half* __restrict__ wos) {
    const int y = blockIdx.y;
    if (y < 3) {
        const float* src = (y == 0) ? q : (y == 1) ? k : v;
        __half* hi = (y == 0) ? qh : (y == 1) ? kh : vh;
        __half* lo = (y == 0) ? ql : (y == 1) ? kl : vl;
        const int n4 = (BS_ * U_) / 4;
        for (int i = blockIdx.x * 256 + threadIdx.x; i < n4; i += 1024 * 256) {
            float4 f = ((const float4*)src)[i];
            uint2 h, l;
            cvt_split_h(f, h, l);
            ((uint2*)hi)[i] = h;
            ((uint2*)lo)[i] = l;
        }
    } else {
        const float* src = (y == 3) ? wq : (y == 4) ? wk : (y == 5) ? wv : wo;
        __half* dst = (y == 3) ? wqs : (y == 4) ? wks : (y == 5) ? wvs : wos;
        const int n4 = (U_ * U_) / 4;
        for (int i = blockIdx.x * 256 + threadIdx.x; i < n4; i += 1024 * 256) {
            float4 f = ((const float4*)src)[i];
            uint2 r;
            cvt_single_h(f, r);
            ((uint2*)dst)[i] = r;
        }
    }
}

// ---------------------------------------------------------------------------
// fp16 asymmetric-split GEMM:  C = (A_hi + A_lo) @ W_s^T + bias
// CTA 128(M) x 256(N), 512 threads, 16 warps (4M x 4N), warp tile 32x64.
// 3-stage cp.async, wait<1>, single barrier per chunk. 2 MMAs per frag pair.
// stage: Ahi@0 (10240), Alo@10240, W@20480 (20480, 256 rows)
// ---------------------------------------------------------------------------
#define ROWB     80
#define ST_ALO   10240u
#define ST_W     20480u
#define STAGE_B  40960
#define G_SMEM   (3 * STAGE_B)
#define NKC      (U_ / 32)

__device__ __forceinline__ void g_issue(uint32_t st,
                                        const __half* __restrict__ Ah,
                                        const __half* __restrict__ Al,
                                        const __half* __restrict__ W,
                                        int bm, int bn, int k0, int tid) {
    const int row = tid >> 2, seg = tid & 3;
    const uint32_t so = (uint32_t)(row * ROWB + seg * 16);
    const size_t ga  = (size_t)(bm + row) * U_ + k0 + seg * 8;
    const size_t gw0 = (size_t)(bn + row) * U_ + k0 + seg * 8;
    const size_t gw1 = (size_t)(bn + 128 + row) * U_ + k0 + seg * 8;
    CP_ASYNC16(st + so,                 Ah + ga);
    CP_ASYNC16(st + ST_ALO + so,        Al + ga);
    CP_ASYNC16(st + ST_W + so,          W + gw0);
    CP_ASYNC16(st + ST_W + 10240u + so, W + gw1);
}

// MODE: 0 = float out + bias; 1 = split hi/lo out, scaled; 2 = single fp16 out
template <int MODE>
__device__ void gemm_h_body(const __half* __restrict__ Ah,
                            const __half* __restrict__ Al,
                            const __half* __restrict__ W,
                            const float* __restrict__ bias, float scale,
                            float* __restrict__ Cf,
                            __half* __restrict__ Ch,
                            __half* __restrict__ Cl) {
    extern __shared__ char smem[];
    const int tid  = threadIdx.x;
    const int lane = tid & 31;
    const int wid  = tid >> 5;
    const int wm   = wid >> 2;          // 0..3
    const int wn   = wid & 3;           // 0..3
    const int bm   = blockIdx.y * 128;
    const int bn   = blockIdx.x * 256;
    const uint32_t sbase = smem_u32(smem);

    float acc[2][8][4];
#pragma unroll
    for (int mf = 0; mf < 2; mf++)
#pragma unroll
        for (int nf = 0; nf < 8; nf++)
#pragma unroll
            for (int r = 0; r < 4; r++) acc[mf][nf][r] = 0.0f;

    const uint32_t a_row  = (uint32_t)(lane & 15);
    const uint32_t a_colh = (uint32_t)(((lane >> 4) & 1) * 16);
    const uint32_t b_nl   = (uint32_t)((lane & 7) + ((lane >> 4) & 1) * 8);
    const uint32_t b_ks   = (uint32_t)(((lane >> 3) & 1) * 16);

    g_issue(sbase, Ah, Al, W, bm, bn, 0, tid);  CP_COMMIT();
    g_issue(sbase + STAGE_B, Ah, Al, W, bm, bn, 32, tid);  CP_COMMIT();

    for (int c = 0; c < NKC; c++) {
        cp_wait<1>();
        __syncthreads();
        if (c + 2 < NKC)
            g_issue(sbase + (uint32_t)((c + 2) % 3) * STAGE_B, Ah, Al, W,
                    bm, bn, (c + 2) * 32, tid);
        CP_COMMIT();

        const uint32_t st = sbase + (uint32_t)(c % 3) * STAGE_B;
#pragma unroll
        for (int ko = 0; ko < 2; ko++) {
            uint32_t ah[2][4], al[2][4];
#pragma unroll
            for (int mf = 0; mf < 2; mf++) {
                uint32_t ad = st + (uint32_t)((wm * 32 + mf * 16 + a_row) * ROWB)
                                 + (uint32_t)(ko * 32) + a_colh;
                LDSM_X4(ah[mf][0], ah[mf][1], ah[mf][2], ah[mf][3], ad);
                LDSM_X4(al[mf][0], al[mf][1], al[mf][2], al[mf][3], ad + ST_ALO);
            }
            uint32_t bh[4][4];
#pragma unroll
            for (int np = 0; np < 4; np++) {
                uint32_t bd = st + ST_W
                            + (uint32_t)((wn * 64 + np * 16 + b_nl) * ROWB)
                            + (uint32_t)(ko * 32) + b_ks;
                LDSM_X4(bh[np][0], bh[np][1], bh[np][2], bh[np][3], bd);
            }
#pragma unroll
            for (int mf = 0; mf < 2; mf++)
#pragma unroll
                for (int nf = 0; nf < 8; nf++) {
                    const uint32_t* bp = &bh[nf >> 1][(nf & 1) * 2];
                    MMA_F16(acc[mf][nf], ah[mf], bp[0], bp[1]);
                    MMA_F16(acc[mf][nf], al[mf], bp[0], bp[1]);
                }
        }
    }

    const int tr = lane >> 2;
    const int tc = (lane & 3) * 2;
#pragma unroll
    for (int mf = 0; mf < 2; mf++) {
#pragma unroll
        for (int nf = 0; nf < 8; nf++) {
            int gr = bm + wm * 32 + mf * 16 + tr;
            int gc = bn + wn * 64 + nf * 8 + tc;
            float2 bv = *(const float2*)(bias + gc);
            float a0 = (acc[mf][nf][0] + bv.x) * scale;
            float a1 = (acc[mf][nf][1] + bv.y) * scale;
            float a2 = (acc[mf][nf][2] + bv.x) * scale;
            float a3 = (acc[mf][nf][3] + bv.y) * scale;
            if (MODE == 1) {
                uint32_t h, l;
                pack_split2h(a0, a1, h, l);
                *(uint32_t*)(Ch + (size_t)gr * U_ + gc) = h;
                *(uint32_t*)(Cl + (size_t)gr * U_ + gc) = l;
                pack_split2h(a2, a3, h, l);
                *(uint32_t*)(Ch + (size_t)(gr + 8) * U_ + gc) = h;
                *(uint32_t*)(Cl + (size_t)(gr + 8) * U_ + gc) = l;
            } else if (MODE == 2) {
                *(uint32_t*)(Ch + (size_t)gr * U_ + gc) =
                    pack_h2(__float2half_rn(a0), __float2half_rn(a1));
                *(uint32_t*)(Ch + (size_t)(gr + 8) * U_ + gc) =
                    pack_h2(__float2half_rn(a2), __float2half_rn(a3));
            } else {
                *(float2*)(Cf + (size_t)gr * U_ + gc)       = make_float2(a0, a1);
                *(float2*)(Cf + (size_t)(gr + 8) * U_ + gc) = make_float2(a2, a3);
            }
        }
    }
}

__global__ __launch_bounds__(512, 1) void gemm_h_qkv(
    const float* __restrict__ bq, const float* __restrict__ bk,
    const float* __restrict__ bv) {
    if (blockIdx.z == 0)
        gemm_h_body<1>(in_q_hi, in_q_lo, w_q_s, bq, 0.125f,
                       nullptr, g_q_hi, g_q_lo);
    else if (blockIdx.z == 1)
        gemm_h_body<2>(in_k_hi, in_k_lo, w_k_s, bk, 1.0f,
                       nullptr, g_k_s, nullptr);
    else
        gemm_h_body<2>(in_v_hi, in_v_lo, w_v_s, bv, 1.0f,
                       nullptr, g_v_s, nullptr);
}

__global__ __launch_bounds__(512, 1) void gemm_h_out(const float* __restrict__ bo,
                                                     float* __restrict__ out) {
    gemm_h_body<0>(g_att_hi, g_att_lo, w_o_s, bo, 1.0f,
                   out, nullptr, nullptr);
}

// ---------------------------------------------------------------------------
// Flash attention, fp16 asymmetric split: Q split (reg-hoisted) / K single,
// P split (regs) / V single.  Round-6 structure: 1 CTA/SM, separate regions.
// smem: Qhi@0, Qlo@18432; stages @36864 + jt&1 * 18432: K@0 (9216), V@9216
// ---------------------------------------------------------------------------
#define AROWB    144
#define AQ_LO_O  18432u
#define AST0     36864u
#define ASTAGE_B 18432u
#define ATT_SMEM 73728

__device__ __forceinline__ void kv_issue(uint32_t buf,
                                         const __half* __restrict__ Ks,
                                         const __half* __restrict__ Vs,
                                         int kbase, int tid) {
#pragma unroll
    for (int i = 0; i < 2; i++) {
        int id  = tid * 2 + i;
        int row = id >> 3, seg = id & 7;
        uint32_t so = (uint32_t)(row * AROWB + seg * 16);
        size_t go = (size_t)(kbase + row) * U_ + seg * 8;
        CP_ASYNC16(buf + so,         Ks + go);
        CP_ASYNC16(buf + 9216u + so, Vs + go);
    }
}

__global__ __launch_bounds__(256, 1) void flash_attn_mma() {
    extern __shared__ char smem[];
    const uint32_t sb = smem_u32(smem);
    const int tid  = threadIdx.x;
    const int lane = tid & 31;
    const int wid  = tid >> 5;
    const int qt   = (int)gridDim.x - 1 - (int)blockIdx.x;   // big tiles first
    const int h    = blockIdx.y;
    const int b    = blockIdx.z;
    const int qbase = qt * 128;

    const size_t head_off = (size_t)b * S_ * U_ + h * DK_;
    const __half* Qh = g_q_hi + head_off + (size_t)qbase * U_;
    const __half* Ql = g_q_lo + head_off + (size_t)qbase * U_;
    const __half* Ks = g_k_s + head_off;
    const __half* Vs = g_v_s + head_off;

    // Q tile cp.async (one-time)
#pragma unroll
    for (int i = 0; i < 4; i++) {
        int id  = tid * 4 + i;
        int row = id >> 3, seg = id & 7;
        uint32_t so = (uint32_t)(row * AROWB + seg * 16);
        size_t go = (size_t)row * U_ + seg * 8;
        CP_ASYNC16(sb + so,           Qh + go);
        CP_ASYNC16(sb + AQ_LO_O + so, Ql + go);
    }
    CP_COMMIT();
    kv_issue(sb + AST0, Ks, Vs, 0, tid);
    CP_COMMIT();

    const uint32_t a_row  = (uint32_t)(lane & 15);
    const uint32_t a_colh = (uint32_t)(((lane >> 4) & 1) * 16);
    const uint32_t b_nl   = (uint32_t)((lane & 7) + ((lane >> 4) & 1) * 8);
    const uint32_t b_ks   = (uint32_t)(((lane >> 3) & 1) * 16);
    const uint32_t v_row  = (uint32_t)(((lane >> 3) & 1) * 8 + (lane & 7));
    const uint32_t v_colh = (uint32_t)(((lane >> 4) & 1) * 16);

    // hoist Q fragments (Q group done; kv0 may still be pending)
    cp_wait<1>();
    __syncthreads();
    uint32_t qh[4][4], ql[4][4];
#pragma unroll
    for (int ko = 0; ko < 4; ko++) {
        uint32_t ad = sb + (uint32_t)((wid * 16 + a_row) * AROWB)
                    + (uint32_t)(ko * 32) + a_colh;
        LDSM_X4(qh[ko][0], qh[ko][1], qh[ko][2], qh[ko][3], ad);
        LDSM_X4(ql[ko][0], ql[ko][1], ql[ko][2], ql[ko][3], ad + AQ_LO_O);
    }

    float m0 = -1e30f, m1 = -1e30f, l0 = 0.0f, l1 = 0.0f;
    float oacc[8][4];
#pragma unroll
    for (int nf = 0; nf < 8; nf++)
#pragma unroll
        for (int r = 0; r < 4; r++) oacc[nf][r] = 0.0f;

    const int njt = 2 * qt + 2;
    for (int jt = 0; jt < njt; jt++) {
        const int kbase = jt * 64;
        cp_wait<0>();
        __syncthreads();
        if (jt + 1 < njt) {
            kv_issue(sb + AST0 + (uint32_t)((jt + 1) & 1) * ASTAGE_B,
                     Ks, Vs, (jt + 1) * 64, tid);
            CP_COMMIT();
        }

        const uint32_t st = sb + AST0 + (uint32_t)(jt & 1) * ASTAGE_B;

        // S = Q K^T  (2 MMAs per fragment: qh*k + ql*k)
        float sacc[8][4];
#pragma unroll
        for (int j = 0; j < 8; j++)
#pragma unroll
            for (int r = 0; r < 4; r++) sacc[j][r] = 0.0f;

#pragma unroll
        for (int ko = 0; ko < 4; ko++) {
#pragma unroll
            for (int np = 0; np < 4; np++) {
                uint32_t kh[4];
                uint32_t bd = st + (uint32_t)((np * 16 + b_nl) * AROWB)
                            + (uint32_t)(ko * 32) + b_ks;
                LDSM_X4(kh[0], kh[1], kh[2], kh[3], bd);
#pragma unroll
                for (int half = 0; half < 2; half++) {
                    float* d = sacc[2 * np + half];
                    const uint32_t* bp = &kh[half * 2];
                    MMA_F16(d, qh[ko], bp[0], bp[1]);
                    MMA_F16(d, ql[ko], bp[0], bp[1]);
                }
            }
        }

        // causal mask on diagonal-overlapping tiles
        if (jt >= 2 * qt) {
            const int row0 = qbase + wid * 16 + (lane >> 2);
            const int row1 = row0 + 8;
#pragma unroll
            for (int j = 0; j < 8; j++) {
                int col = kbase + 8 * j + 2 * (lane & 3);
                if (col > row0)     sacc[j][0] = -1e9f;
                if (col + 1 > row0) sacc[j][1] = -1e9f;
                if (col > row1)     sacc[j][2] = -1e9f;
                if (col + 1 > row1) sacc[j][3] = -1e9f;
            }
        }

        // online softmax (in-warp quad reductions)
        float rm0 = -1e30f, rm1 = -1e30f;
#pragma unroll
        for (int j = 0; j < 8; j++) {
            rm0 = fmaxf(rm0, fmaxf(sacc[j][0], sacc[j][1]));
            rm1 = fmaxf(rm1, fmaxf(sacc[j][2], sacc[j][3]));
        }
        rm0 = fmaxf(rm0, __shfl_xor_sync(0xffffffffu, rm0, 1));
        rm0 = fmaxf(rm0, __shfl_xor_sync(0xffffffffu, rm0, 2));
        rm1 = fmaxf(rm1, __shfl_xor_sync(0xffffffffu, rm1, 1));
        rm1 = fmaxf(rm1, __shfl_xor_sync(0xffffffffu, rm1, 2));
        float mn0 = fmaxf(m0, rm0), mn1 = fmaxf(m1, rm1);
        float corr0 = __expf(m0 - mn0), corr1 = __expf(m1 - mn1);
        m0 = mn0; m1 = mn1;
        float rs0 = 0.0f, rs1 = 0.0f;
#pragma unroll
        for (int j = 0; j < 8; j++) {
            float p0 = __expf(sacc[j][0] - mn0);
            float p1 = __expf(sacc[j][1] - mn0);
            float p2 = __expf(sacc[j][2] - mn1);
            float p3 = __expf(sacc[j][3] - mn1);
            sacc[j][0] = p0; sacc[j][1] = p1; sacc[j][2] = p2; sacc[j][3] = p3;
            rs0 += p0 + p1; rs1 += p2 + p3;
        }
        rs0 += __shfl_xor_sync(0xffffffffu, rs0, 1);
        rs0 += __shfl_xor_sync(0xffffffffu, rs0, 2);
        rs1 += __shfl_xor_sync(0xffffffffu, rs1, 1);
        rs1 += __shfl_xor_sync(0xffffffffu, rs1, 2);
        l0 = l0 * corr0 + rs0;
        l1 = l1 * corr1 + rs1;
#pragma unroll
        for (int nf = 0; nf < 8; nf++) {
            oacc[nf][0] *= corr0; oacc[nf][1] *= corr0;
            oacc[nf][2] *= corr1; oacc[nf][3] *= corr1;
        }

        // O += P V  (P split in regs, V single)
#pragma unroll
        for (int t = 0; t < 4; t++) {
            uint32_t ph[4], pl[4];
            pack_split2h(sacc[2 * t][0],     sacc[2 * t][1],     ph[0], pl[0]);
            pack_split2h(sacc[2 * t][2],     sacc[2 * t][3],     ph[1], pl[1]);
            pack_split2h(sacc[2 * t + 1][0], sacc[2 * t + 1][1], ph[2], pl[2]);
            pack_split2h(sacc[2 * t + 1][2], sacc[2 * t + 1][3], ph[3], pl[3]);
            uint32_t vh[4][4];
#pragma unroll
            for (int g = 0; g < 4; g++) {
                uint32_t va = st + 9216u + (uint32_t)((t * 16 + v_row) * AROWB)
                            + v_colh + (uint32_t)(g * 32);
                LDSM_X4_T(vh[g][0], vh[g][1], vh[g][2], vh[g][3], va);
            }
#pragma unroll
            for (int nf = 0; nf < 8; nf++) {
                const uint32_t* bp = &vh[nf >> 1][(nf & 1) * 2];
                MMA_F16(oacc[nf], ph, bp[0], bp[1]);
                MMA_F16(oacc[nf], pl, bp[0], bp[1]);
            }
        }
    }

    // epilogue: normalize, split, write g_att hi/lo
    const float inv0 = 1.0f / l0, inv1 = 1.0f / l1;
    const int row0 = qbase + wid * 16 + (lane >> 2);
    const size_t obase = (size_t)b * S_ * U_ + (size_t)row0 * U_ + h * DK_ + 2 * (lane & 3);
#pragma unroll
    for (int nf = 0; nf < 8; nf++) {
        uint32_t h32, l32;
        pack_split2h(oacc[nf][0] * inv0, oacc[nf][1] * inv0, h32, l32);
        *(uint32_t*)(g_att_hi + obase + 8 * nf) = h32;
        *(uint32_t*)(g_att_lo + obase + 8 * nf) = l32;
        pack_split2h(oacc[nf][2] * inv1, oacc[nf][3] * inv1, h32, l32);
        *(uint32_t*)(g_att_hi + obase + 8 * (size_t)U_ + 8 * nf) = h32;
        *(uint32_t*)(g_att_lo + obase + 8 * (size_t)U_ + 8 * nf) = l32;
    }
}

// ---------------------------------------------------------------------------
extern "C" void kernel_launch(void* const* d_in, const int* in_sizes, int n_in,
                              void* d_out, int out_size) {
    const float* query = (const float*)d_in[0];
    const float* key   = (const float*)d_in[1];
    const float* value = (const float*)d_in[2];
    const float* Wq = (const float*)d_in[4];
    const float* bq = (const float*)d_in[5];
    const float* Wk = (const float*)d_in[6];
    const float* bk = (const float*)d_in[7];
    const float* Wv = (const float*)d_in[8];
    const float* bv = (const float*)d_in[9];
    const float* Wo = (const float*)d_in[10];
    const float* bo = (const float*)d_in[11];
    float* out = (float*)d_out;

    cudaFuncSetAttribute(gemm_h_qkv, cudaFuncAttributeMaxDynamicSharedMemorySize, G_SMEM);
    cudaFuncSetAttribute(gemm_h_out, cudaFuncAttributeMaxDynamicSharedMemorySize, G_SMEM);
    cudaFuncSetAttribute(flash_attn_mma, cudaFuncAttributeMaxDynamicSharedMemorySize, ATT_SMEM);

    static __half *p_iqh = nullptr, *p_iql, *p_ikh, *p_ikl, *p_ivh, *p_ivl;
    static __half *p_wq, *p_wk, *p_wv, *p_wo;
    if (!p_iqh) {
        cudaGetSymbolAddress((void**)&p_iqh, in_q_hi);
        cudaGetSymbolAddress((void**)&p_iql, in_q_lo);
        cudaGetSymbolAddress((void**)&p_ikh, in_k_hi);
        cudaGetSymbolAddress((void**)&p_ikl, in_k_lo);
        cudaGetSymbolAddress((void**)&p_ivh, in_v_hi);
        cudaGetSymbolAddress((void**)&p_ivl, in_v_lo);
        cudaGetSymbolAddress((void**)&p_wq, w_q_s);
        cudaGetSymbolAddress((void**)&p_wk, w_k_s);
        cudaGetSymbolAddress((void**)&p_wv, w_v_s);
        cudaGetSymbolAddress((void**)&p_wo, w_o_s);
    }

    dim3 gc(1024, 7, 1);
    convert_all_kernel<<<gc, 256>>>(query, key, value, Wq, Wk, Wv, Wo,
                                    p_iqh, p_iql, p_ikh, p_ikl, p_ivh, p_ivl,
                                    p_wq, p_wk, p_wv, p_wo);

    dim3 gq(U_ / 256, BS_ / 128, 3);
    gemm_h_qkv<<<gq, 512, G_SMEM>>>(bq, bk, bv);

    dim3 ga(S_ / 128, H_, B_);
    flash_attn_mma<<<ga, 256, ATT_SMEM>>>();

    dim3 go(U_ / 256, BS_ / 128, 1);
    gemm_h_out<<<go, 512, G_SMEM>>>(bo, out);
}

// round 12
// speedup vs baseline: 1.3037x; 1.3037x over previous
#include <cuda_runtime.h>
#include <cuda_bf16.h>
#include <cstdint>

#define B_  2
#define S_  2048
#define U_  1024
#define H_  16
#define DK_ 64
#define BS_ (B_ * S_)

// persistent split-bf16 scratch (allocation-free rule: __device__ globals)
__device__ __nv_bfloat16 in_q_hi[BS_ * U_], in_q_lo[BS_ * U_];
__device__ __nv_bfloat16 in_k_hi[BS_ * U_], in_k_lo[BS_ * U_];
__device__ __nv_bfloat16 in_v_hi[BS_ * U_], in_v_lo[BS_ * U_];
__device__ __nv_bfloat16 w_q_hi[U_ * U_], w_q_lo[U_ * U_];
__device__ __nv_bfloat16 w_k_hi[U_ * U_], w_k_lo[U_ * U_];
__device__ __nv_bfloat16 w_v_hi[U_ * U_], w_v_lo[U_ * U_];
__device__ __nv_bfloat16 w_o_hi[U_ * U_], w_o_lo[U_ * U_];
__device__ __nv_bfloat16 g_q_hi[BS_ * U_], g_q_lo[BS_ * U_];
__device__ __nv_bfloat16 g_k_hi[BS_ * U_], g_k_lo[BS_ * U_];
__device__ __nv_bfloat16 g_v_hi[BS_ * U_], g_v_lo[BS_ * U_];
__device__ __nv_bfloat16 g_att_hi[BS_ * U_], g_att_lo[BS_ * U_];

// ---------------------------------------------------------------------------
// helpers
// ---------------------------------------------------------------------------
__device__ __forceinline__ uint32_t smem_u32(const void* p) {
    uint32_t a;
    asm("{ .reg .u64 t; cvta.to.shared.u64 t, %1; cvt.u32.u64 %0, t; }" : "=r"(a) : "l"(p));
    return a;
}

#define LDSM_X4(r0, r1, r2, r3, addr)                                         \
    asm volatile("ldmatrix.sync.aligned.m8n8.x4.shared.b16 {%0,%1,%2,%3}, [%4];" \
        : "=r"(r0), "=r"(r1), "=r"(r2), "=r"(r3) : "r"(addr))

#define LDSM_X4_T(r0, r1, r2, r3, addr)                                       \
    asm volatile("ldmatrix.sync.aligned.m8n8.x4.trans.shared.b16 {%0,%1,%2,%3}, [%4];" \
        : "=r"(r0), "=r"(r1), "=r"(r2), "=r"(r3) : "r"(addr))

#define MMA_BF16(d, a, b0, b1)                                                \
    asm volatile("mma.sync.aligned.m16n8k16.row.col.f32.bf16.bf16.f32 "       \
        "{%0,%1,%2,%3},{%4,%5,%6,%7},{%8,%9},{%0,%1,%2,%3};"                  \
        : "+f"((d)[0]), "+f"((d)[1]), "+f"((d)[2]), "+f"((d)[3])              \
        : "r"((a)[0]), "r"((a)[1]), "r"((a)[2]), "r"((a)[3]), "r"(b0), "r"(b1))

#define CP_ASYNC16(saddr, gptr) \
    asm volatile("cp.async.cg.shared.global [%0], [%1], 16;" :: "r"(saddr), "l"(gptr) : "memory")
#define CP_COMMIT() asm volatile("cp.async.commit_group;" ::: "memory")
template <int N> __device__ __forceinline__ void cp_wait() {
    asm volatile("cp.async.wait_group %0;" :: "n"(N) : "memory");
}

// mbarrier primitives (base ISA; NOT tcgen05-family)
#define MBARRIER_INIT(addr, cnt) \
    asm volatile("mbarrier.init.shared.b64 [%0], %1;" :: "r"(addr), "r"(cnt) : "memory")
#define MBARRIER_ARRIVE(addr) do { unsigned long long _t;                      \
    asm volatile("mbarrier.arrive.shared.b64 %0, [%1];" : "=l"(_t) : "r"(addr) : "memory"); } while (0)
// .noinc is load-bearing: pending count NOT incremented, so the 512-count
// barrier is drained by 512 async arrivals (round-11 deadlock fix).
#define CP_MBAR_ARRIVE(addr) \
    asm volatile("cp.async.mbarrier.arrive.noinc.shared.b64 [%0];" :: "r"(addr) : "memory")
#define MBARRIER_WAIT_PARITY(addr, par) do {                                  \
    uint32_t _m = (addr); uint32_t _p = (par); uint32_t _done;                \
    asm volatile("{ .reg .pred p; mbarrier.try_wait.parity.acquire.cta.shared::cta.b64 p, [%1], %2; selp.b32 %0,1,0,p; }" \
        : "=r"(_done) : "r"(_m), "r"(_p) : "memory");                         \
    if (!_done) {                                                             \
        asm volatile("{ .reg .pred P1; WAIT_LOOP_%=: mbarrier.try_wait.parity.acquire.cta.shared::cta.b64 P1, [%0], %1, 0x989680; @P1 bra.uni WAIT_DONE_%=; bra.uni WAIT_LOOP_%=; WAIT_DONE_%=: }" \
            :: "r"(_m), "r"(_p) : "memory");                                  \
    } } while (0)

__device__ __forceinline__ uint32_t pack_bf16(__nv_bfloat16 a, __nv_bfloat16 b) {
    uint32_t ua = *reinterpret_cast<unsigned short*>(&a);
    uint32_t ub = *reinterpret_cast<unsigned short*>(&b);
    return ua | (ub << 16);
}

__device__ __forceinline__ void cvt_split(const float4& f, uint2& hi, uint2& lo) {
    __nv_bfloat16 h0 = __float2bfloat16(f.x);
    __nv_bfloat16 h1 = __float2bfloat16(f.y);
    __nv_bfloat16 h2 = __float2bfloat16(f.z);
    __nv_bfloat16 h3 = __float2bfloat16(f.w);
    __nv_bfloat16 l0 = __float2bfloat16(f.x - __bfloat162float(h0));
    __nv_bfloat16 l1 = __float2bfloat16(f.y - __bfloat162float(h1));
    __nv_bfloat16 l2 = __float2bfloat16(f.z - __bfloat162float(h2));
    __nv_bfloat16 l3 = __float2bfloat16(f.w - __bfloat162float(h3));
    hi.x = pack_bf16(h0, h1); hi.y = pack_bf16(h2, h3);
    lo.x = pack_bf16(l0, l1); lo.y = pack_bf16(l2, l3);
}

__device__ __forceinline__ void pack_split2(float a, float b, uint32_t& hi, uint32_t& lo) {
    __nv_bfloat16 ha = __float2bfloat16(a), hb = __float2bfloat16(b);
    __nv_bfloat16 la = __float2bfloat16(a - __bfloat162float(ha));
    __nv_bfloat16 lb = __float2bfloat16(b - __bfloat162float(hb));
    hi = pack_bf16(ha, hb); lo = pack_bf16(la, lb);
}

// ---------------------------------------------------------------------------
// one-shot pre-pass: all 7 fp32 arrays -> (hi, lo) bf16.  blockIdx.y selects.
// ---------------------------------------------------------------------------
__global__ __launch_bounds__(256) void convert_all_kernel(
    const float* __restrict__ q, const float* __restrict__ k,
    const float* __restrict__ v, const float* __restrict__ wq,
    const float* __restrict__ wk, const float* __restrict__ wv,
    const float* __restrict__ wo,
    __nv_bfloat16* __restrict__ qh, __nv_bfloat16* __restrict__ ql,
    __nv_bfloat16* __restrict__ kh, __nv_bfloat16* __restrict__ kl,
    __nv_bfloat16* __restrict__ vh, __nv_bfloat16* __restrict__ vl,
    __nv_bfloat16* __restrict__ wqh, __nv_bfloat16* __restrict__ wql,
    __nv_bfloat16* __restrict__ wkh, __nv_bfloat16* __restrict__ wkl,
    __nv_bfloat16* __restrict__ wvh, __nv_bfloat16* __restrict__ wvl,
    __nv_bfloat16* __restrict__ woh, __nv_bfloat16* __restrict__ wol) {
    const float* src; __nv_bfloat16* hi; __nv_bfloat16* lo; int n4;
    switch (blockIdx.y) {
        case 0: src = q;  hi = qh;  lo = ql;  n4 = (BS_ * U_) / 4; break;
        case 1: src = k;  hi = kh;  lo = kl;  n4 = (BS_ * U_) / 4; break;
        case 2: src = v;  hi = vh;  lo = vl;  n4 = (BS_ * U_) / 4; break;
        case 3: src = wq; hi = wqh; lo = wql; n4 = (U_ * U_) / 4; break;
        case 4: src = wk; hi = wkh; lo = wkl; n4 = (U_ * U_) / 4; break;
        case 5: src = wv; hi = wvh; lo = wvl; n4 = (U_ * U_) / 4; break;
        default: src = wo; hi = woh; lo = wol; n4 = (U_ * U_) / 4; break;
    }
    for (int i = blockIdx.x * 256 + threadIdx.x; i < n4; i += 1024 * 256) {
        float4 f = ((const float4*)src)[i];
        uint2 h, l;
        cvt_split(f, h, l);
        ((uint2*)hi)[i] = h;
        ((uint2*)lo)[i] = l;
    }
}

// ---------------------------------------------------------------------------
// split-bf16 GEMM, 3-stage cp.async with per-stage mbarrier pipeline
// (NO per-chunk __syncthreads).  CTA 128(M) x 256(N), 512 threads,
// 16 warps (4M x 4N), warp tile 32x64, K-chunk 32.
// stage: Ahi@0 (10240), Alo@10240, Whi@20480 (20480), Wlo@40960
// full[s]: count=512, armed by cp.async.mbarrier.arrive.noinc per thread.
// empty[s]: count=16, armed by lane0 of each warp after MMAs consume stage.
// ---------------------------------------------------------------------------
#define ROWB     80
#define ST_ALO   10240u
#define ST_WHI   20480u
#define ST_WLO   40960u
#define STAGE_B  61440
#define G_SMEM   (3 * STAGE_B)
#define NKC      (U_ / 32)

__device__ __forceinline__ void g_issue(uint32_t st,
                                        const __nv_bfloat16* __restrict__ Ah,
                                        const __nv_bfloat16* __restrict__ Al,
                                        const __nv_bfloat16* __restrict__ Wh,
                                        const __nv_bfloat16* __restrict__ Wl,
                                        int bm, int bn, int k0, int tid) {
    const int row = tid >> 2, seg = tid & 3;
    const uint32_t so = (uint32_t)(row * ROWB + seg * 16);
    const size_t ga  = (size_t)(bm + row) * U_ + k0 + seg * 8;
    const size_t gw0 = (size_t)(bn + row) * U_ + k0 + seg * 8;
    const size_t gw1 = (size_t)(bn + 128 + row) * U_ + k0 + seg * 8;
    CP_ASYNC16(st + so,                    Ah + ga);
    CP_ASYNC16(st + ST_ALO + so,           Al + ga);
    CP_ASYNC16(st + ST_WHI + so,           Wh + gw0);
    CP_ASYNC16(st + ST_WHI + 10240u + so,  Wh + gw1);
    CP_ASYNC16(st + ST_WLO + so,           Wl + gw0);
    CP_ASYNC16(st + ST_WLO + 10240u + so,  Wl + gw1);
}

template <bool SPLIT_OUT>
__device__ void gemm_bf_body(const __nv_bfloat16* __restrict__ Ah,
                             const __nv_bfloat16* __restrict__ Al,
                             const __nv_bfloat16* __restrict__ Wh,
                             const __nv_bfloat16* __restrict__ Wl,
                             const float* __restrict__ bias, float scale,
                             float* __restrict__ Cf,
                             __nv_bfloat16* __restrict__ Ch,
                             __nv_bfloat16* __restrict__ Cl) {
    extern __shared__ char smem[];
    __shared__ __align__(8) uint64_t s_mbar[6];   // full[0..2], empty[0..2]
    const int tid  = threadIdx.x;
    const int lane = tid & 31;
    const int wid  = tid >> 5;
    const int wm   = wid >> 2;          // 0..3
    const int wn   = wid & 3;           // 0..3
    const int bm   = blockIdx.y * 128;
    const int bn   = blockIdx.x * 256;
    const uint32_t sbase = smem_u32(smem);
    const uint32_t mb    = smem_u32(s_mbar);

    if (tid == 0) {
#pragma unroll
        for (int s = 0; s < 3; s++) {
            MBARRIER_INIT(mb + 8u * s, 512u);        // full
            MBARRIER_INIT(mb + 24u + 8u * s, 16u);   // empty
        }
    }
    __syncthreads();

    float acc[2][8][4];
#pragma unroll
    for (int mf = 0; mf < 2; mf++)
#pragma unroll
        for (int nf = 0; nf < 8; nf++)
#pragma unroll
            for (int r = 0; r < 4; r++) acc[mf][nf][r] = 0.0f;

    const uint32_t a_row  = (uint32_t)(lane & 15);
    const uint32_t a_colh = (uint32_t)(((lane >> 4) & 1) * 16);
    const uint32_t b_nl   = (uint32_t)((lane & 7) + ((lane >> 4) & 1) * 8);
    const uint32_t b_ks   = (uint32_t)(((lane >> 3) & 1) * 16);

    // prologue: chunks 0,1
    g_issue(sbase, Ah, Al, Wh, Wl, bm, bn, 0, tid);
    CP_MBAR_ARRIVE(mb + 0u);
    g_issue(sbase + STAGE_B, Ah, Al, Wh, Wl, bm, bn, 32, tid);
    CP_MBAR_ARRIVE(mb + 8u);

    for (int c = 0; c < NKC; c++) {
        const int s = c % 3;
        MBARRIER_WAIT_PARITY(mb + 8u * (uint32_t)s, (uint32_t)((c / 3) & 1));

        const uint32_t st = sbase + (uint32_t)s * STAGE_B;
#pragma unroll
        for (int ko = 0; ko < 2; ko++) {
            uint32_t ah[2][4], al[2][4];
#pragma unroll
            for (int mf = 0; mf < 2; mf++) {
                uint32_t ad = st + (uint32_t)((wm * 32 + mf * 16 + a_row) * ROWB)
                                 + (uint32_t)(ko * 32) + a_colh;
                LDSM_X4(ah[mf][0], ah[mf][1], ah[mf][2], ah[mf][3], ad);
                LDSM_X4(al[mf][0], al[mf][1], al[mf][2], al[mf][3], ad + ST_ALO);
            }
            uint32_t bh[4][4], bl[4][4];
#pragma unroll
            for (int np = 0; np < 4; np++) {
                uint32_t bd = st + ST_WHI
                            + (uint32_t)((wn * 64 + np * 16 + b_nl) * ROWB)
                            + (uint32_t)(ko * 32) + b_ks;
                LDSM_X4(bh[np][0], bh[np][1], bh[np][2], bh[np][3], bd);
                LDSM_X4(bl[np][0], bl[np][1], bl[np][2], bl[np][3], bd + 20480u);
            }
#pragma unroll
            for (int mf = 0; mf < 2; mf++)
#pragma unroll
                for (int nf = 0; nf < 8; nf++) {
                    const uint32_t* bhp = &bh[nf >> 1][(nf & 1) * 2];
                    const uint32_t* blp = &bl[nf >> 1][(nf & 1) * 2];
                    MMA_BF16(acc[mf][nf], ah[mf], bhp[0], bhp[1]);
                    MMA_BF16(acc[mf][nf], ah[mf], blp[0], blp[1]);
                    MMA_BF16(acc[mf][nf], al[mf], bhp[0], bhp[1]);
                }
        }
        // all LDSM smem reads for this stage are complete (consumed by MMAs)
        if (lane == 0) MBARRIER_ARRIVE(mb + 24u + 8u * (uint32_t)s);

        if (c + 2 < NKC) {
            const int n = c + 2, sn = n % 3;
            if (n >= 3)
                MBARRIER_WAIT_PARITY(mb + 24u + 8u * (uint32_t)sn,
                                     (uint32_t)(((n / 3) - 1) & 1));
            g_issue(sbase + (uint32_t)sn * STAGE_B, Ah, Al, Wh, Wl,
                    bm, bn, n * 32, tid);
            CP_MBAR_ARRIVE(mb + 8u * (uint32_t)sn);
        }
    }

    const int tr = lane >> 2;
    const int tc = (lane & 3) * 2;
#pragma unroll
    for (int mf = 0; mf < 2; mf++) {
#pragma unroll
        for (int nf = 0; nf < 8; nf++) {
            int gr = bm + wm * 32 + mf * 16 + tr;
            int gc = bn + wn * 64 + nf * 8 + tc;
            float2 bv = *(const float2*)(bias + gc);
            if (SPLIT_OUT) {
                float a0 = (acc[mf][nf][0] + bv.x) * scale;
                float a1 = (acc[mf][nf][1] + bv.y) * scale;
                float a2 = (acc[mf][nf][2] + bv.x) * scale;
                float a3 = (acc[mf][nf][3] + bv.y) * scale;
                uint32_t h, l;
                pack_split2(a0, a1, h, l);
                *(uint32_t*)(Ch + (size_t)gr * U_ + gc) = h;
                *(uint32_t*)(Cl + (size_t)gr * U_ + gc) = l;
                pack_split2(a2, a3, h, l);
                *(uint32_t*)(Ch + (size_t)(gr + 8) * U_ + gc) = h;
                *(uint32_t*)(Cl + (size_t)(gr + 8) * U_ + gc) = l;
            } else {
                float2 o0 = make_float2(acc[mf][nf][0] + bv.x, acc[mf][nf][1] + bv.y);
                float2 o1 = make_float2(acc[mf][nf][2] + bv.x, acc[mf][nf][3] + bv.y);
                *(float2*)(Cf + (size_t)gr * U_ + gc)       = o0;
                *(float2*)(Cf + (size_t)(gr + 8) * U_ + gc) = o1;
            }
        }
    }
}

__global__ __launch_bounds__(512, 1) void gemm_bf_qkv_b(
    const float* __restrict__ bq, const float* __restrict__ bk,
    const float* __restrict__ bv) {
    if (blockIdx.z == 0)
        gemm_bf_body<true>(in_q_hi, in_q_lo, w_q_hi, w_q_lo, bq, 0.125f,
                           nullptr, g_q_hi, g_q_lo);
    else if (blockIdx.z == 1)
        gemm_bf_body<true>(in_k_hi, in_k_lo, w_k_hi, w_k_lo, bk, 1.0f,
                           nullptr, g_k_hi, g_k_lo);
    else
        gemm_bf_body<true>(in_v_hi, in_v_lo, w_v_hi, w_v_lo, bv, 1.0f,
                           nullptr, g_v_hi, g_v_lo);
}

__global__ __launch_bounds__(512, 1) void gemm_bf_out(const float* __restrict__ bo,
                                                      float* __restrict__ out) {
    gemm_bf_body<false>(g_att_hi, g_att_lo, w_o_hi, w_o_lo, bo, 1.0f,
                        out, nullptr, nullptr);
}

// ---------------------------------------------------------------------------
// Flash attention, split-bf16 mma.sync (round-6 exact: 1 CTA/SM, separate
// Q region + double-buffered kv stages, one barrier per kv tile).
// smem: Qhi@0, Qlo@18432; stages @36864 + (jt&1)*36864:
//       Khi@0, Klo@9216, Vhi@18432, Vlo@27648 (row stride 144B)
// ---------------------------------------------------------------------------
#define AROWB    144
#define AQ_LO_O  18432u
#define AST0     36864u
#define ASTAGE_B 36864u
#define ATT_SMEM 110592

__device__ __forceinline__ void kv_issue(uint32_t buf,
                                         const __nv_bfloat16* __restrict__ Kh,
                                         const __nv_bfloat16* __restrict__ Kl,
                                         const __nv_bfloat16* __restrict__ Vh,
                                         const __nv_bfloat16* __restrict__ Vl,
                                         int kbase, int tid) {
#pragma unroll
    for (int i = 0; i < 2; i++) {
        int id  = tid * 2 + i;
        int row = id >> 3, seg = id & 7;
        uint32_t so = (uint32_t)(row * AROWB + seg * 16);
        size_t go = (size_t)(kbase + row) * U_ + seg * 8;
        CP_ASYNC16(buf + so,          Kh + go);
        CP_ASYNC16(buf + 9216u + so,  Kl + go);
        CP_ASYNC16(buf + 18432u + so, Vh + go);
        CP_ASYNC16(buf + 27648u + so, Vl + go);
    }
}

__global__ __launch_bounds__(256, 1) void flash_attn_mma() {
    extern __shared__ char smem[];
    const uint32_t sb = smem_u32(smem);
    const int tid  = threadIdx.x;
    const int lane = tid & 31;
    const int wid  = tid >> 5;
    const int qt   = (int)gridDim.x - 1 - (int)blockIdx.x;   // big tiles first
    const int h    = blockIdx.y;
    const int b    = blockIdx.z;
    const int qbase = qt * 128;

    const size_t head_off = (size_t)b * S_ * U_ + h * DK_;
    const __nv_bfloat16* Qh = g_q_hi + head_off + (size_t)qbase * U_;
    const __nv_bfloat16* Ql = g_q_lo + head_off + (size_t)qbase * U_;
    const __nv_bfloat16* Kh = g_k_hi + head_off;
    const __nv_bfloat16* Kl = g_k_lo + head_off;
    const __nv_bfloat16* Vh = g_v_hi + head_off;
    const __nv_bfloat16* Vl = g_v_lo + head_off;

    // Q tile cp.async (one-time)
#pragma unroll
    for (int i = 0; i < 4; i++) {
        int id  = tid * 4 + i;
        int row = id >> 3, seg = id & 7;
        uint32_t so = (uint32_t)(row * AROWB + seg * 16);
        size_t go = (size_t)row * U_ + seg * 8;
        CP_ASYNC16(sb + so,           Qh + go);
        CP_ASYNC16(sb + AQ_LO_O + so, Ql + go);
    }
    CP_COMMIT();
    kv_issue(sb + AST0, Kh, Kl, Vh, Vl, 0, tid);
    CP_COMMIT();

    const uint32_t a_row  = (uint32_t)(lane & 15);
    const uint32_t a_colh = (uint32_t)(((lane >> 4) & 1) * 16);
    const uint32_t b_nl   = (uint32_t)((lane & 7) + ((lane >> 4) & 1) * 8);
    const uint32_t b_ks   = (uint32_t)(((lane >> 3) & 1) * 16);
    const uint32_t v_row  = (uint32_t)(((lane >> 3) & 1) * 8 + (lane & 7));
    const uint32_t v_colh = (uint32_t)(((lane >> 4) & 1) * 16);

    // hoist Q fragments (Q group done; kv0 may still be pending)
    cp_wait<1>();
    __syncthreads();
    uint32_t qh[4][4], ql[4][4];
#pragma unroll
    for (int ko = 0; ko < 4; ko++) {
        uint32_t ad = sb + (uint32_t)((wid * 16 + a_row) * AROWB)
                    + (uint32_t)(ko * 32) + a_colh;
        LDSM_X4(qh[ko][0], qh[ko][1], qh[ko][2], qh[ko][3], ad);
        LDSM_X4(ql[ko][0], ql[ko][1], ql[ko][2], ql[ko][3], ad + AQ_LO_O);
    }

    float m0 = -1e30f, m1 = -1e30f, l0 = 0.0f, l1 = 0.0f;
    float oacc[8][4];
#pragma unroll
    for (int nf = 0; nf < 8; nf++)
#pragma unroll
        for (int r = 0; r < 4; r++) oacc[nf][r] = 0.0f;

    const int njt = 2 * qt + 2;
    for (int jt = 0; jt < njt; jt++) {
        const int kbase = jt * 64;
        cp_wait<0>();
        __syncthreads();
        if (jt + 1 < njt) {
            kv_issue(sb + AST0 + (uint32_t)((jt + 1) & 1) * ASTAGE_B,
                     Kh, Kl, Vh, Vl, (jt + 1) * 64, tid);
            CP_COMMIT();
        }

        const uint32_t st = sb + AST0 + (uint32_t)(jt & 1) * ASTAGE_B;

        // S = Q K^T
        float sacc[8][4];
#pragma unroll
        for (int j = 0; j < 8; j++)
#pragma unroll
            for (int r = 0; r < 4; r++) sacc[j][r] = 0.0f;

#pragma unroll
        for (int ko = 0; ko < 4; ko++) {
#pragma unroll
            for (int np = 0; np < 4; np++) {
                uint32_t kh[4], kl[4];
                uint32_t bd = st + (uint32_t)((np * 16 + b_nl) * AROWB)
                            + (uint32_t)(ko * 32) + b_ks;
                LDSM_X4(kh[0], kh[1], kh[2], kh[3], bd);
                LDSM_X4(kl[0], kl[1], kl[2], kl[3], bd + 9216u);
#pragma unroll
                for (int half = 0; half < 2; half++) {
                    float* d = sacc[2 * np + half];
                    const uint32_t* bh = &kh[half * 2];
                    const uint32_t* bl = &kl[half * 2];
                    MMA_BF16(d, qh[ko], bh[0], bh[1]);
                    MMA_BF16(d, qh[ko], bl[0], bl[1]);
                    MMA_BF16(d, ql[ko], bh[0], bh[1]);
                }
            }
        }

        // causal mask on diagonal-overlapping tiles
        if (jt >= 2 * qt) {
            const int row0 = qbase + wid * 16 + (lane >> 2);
            const int row1 = row0 + 8;
#pragma unroll
            for (int j = 0; j < 8; j++) {
                int col = kbase + 8 * j + 2 * (lane & 3);
                if (col > row0)     sacc[j][0] = -1e9f;
                if (col + 1 > row0) sacc[j][1] = -1e9f;
                if (col > row1)     sacc[j][2] = -1e9f;
                if (col + 1 > row1) sacc[j][3] = -1e9f;
            }
        }

        // online softmax (in-warp quad reductions)
        float rm0 = -1e30f, rm1 = -1e30f;
#pragma unroll
        for (int j = 0; j < 8; j++) {
            rm0 = fmaxf(rm0, fmaxf(sacc[j][0], sacc[j][1]));
            rm1 = fmaxf(rm1, fmaxf(sacc[j][2], sacc[j][3]));
        }
        rm0 = fmaxf(rm0, __shfl_xor_sync(0xffffffffu, rm0, 1));
        rm0 = fmaxf(rm0, __shfl_xor_sync(0xffffffffu, rm0, 2));
        rm1 = fmaxf(rm1, __shfl_xor_sync(0xffffffffu, rm1, 1));
        rm1 = fmaxf(rm1, __shfl_xor_sync(0xffffffffu, rm1, 2));
        float mn0 = fmaxf(m0, rm0), mn1 = fmaxf(m1, rm1);
        float corr0 = __expf(m0 - mn0), corr1 = __expf(m1 - mn1);
        m0 = mn0; m1 = mn1;
        float rs0 = 0.0f, rs1 = 0.0f;
#pragma unroll
        for (int j = 0; j < 8; j++) {
            float p0 = __expf(sacc[j][0] - mn0);
            float p1 = __expf(sacc[j][1] - mn0);
            float p2 = __expf(sacc[j][2] - mn1);
            float p3 = __expf(sacc[j][3] - mn1);
            sacc[j][0] = p0; sacc[j][1] = p1; sacc[j][2] = p2; sacc[j][3] = p3;
            rs0 += p0 + p1; rs1 += p2 + p3;
        }
        rs0 += __shfl_xor_sync(0xffffffffu, rs0, 1);
        rs0 += __shfl_xor_sync(0xffffffffu, rs0, 2);
        rs1 += __shfl_xor_sync(0xffffffffu, rs1, 1);
        rs1 += __shfl_xor_sync(0xffffffffu, rs1, 2);
        l0 = l0 * corr0 + rs0;
        l1 = l1 * corr1 + rs1;
#pragma unroll
        for (int nf = 0; nf < 8; nf++) {
            oacc[nf][0] *= corr0; oacc[nf][1] *= corr0;
            oacc[nf][2] *= corr1; oacc[nf][3] *= corr1;
        }

        // O += P V
#pragma unroll
        for (int t = 0; t < 4; t++) {
            uint32_t ph[4], pl[4];
            pack_split2(sacc[2 * t][0],     sacc[2 * t][1],     ph[0], pl[0]);
            pack_split2(sacc[2 * t][2],     sacc[2 * t][3],     ph[1], pl[1]);
            pack_split2(sacc[2 * t + 1][0], sacc[2 * t + 1][1], ph[2], pl[2]);
            pack_split2(sacc[2 * t + 1][2], sacc[2 * t + 1][3], ph[3], pl[3]);
            uint32_t vh[4][4], vl[4][4];
#pragma unroll
            for (int g = 0; g < 4; g++) {
                uint32_t va = st + 18432u + (uint32_t)((t * 16 + v_row) * AROWB)
                            + v_colh + (uint32_t)(g * 32);
                LDSM_X4_T(vh[g][0], vh[g][1], vh[g][2], vh[g][3], va);
                LDSM_X4_T(vl[g][0], vl[g][1], vl[g][2], vl[g][3], va + 9216u);
            }
#pragma unroll
            for (int nf = 0; nf < 8; nf++) {
                const int g = nf >> 1;
                const uint32_t* bh = &vh[g][(nf & 1) * 2];
                const uint32_t* bl = &vl[g][(nf & 1) * 2];
                MMA_BF16(oacc[nf], ph, bh[0], bh[1]);
                MMA_BF16(oacc[nf], pl, bh[0], bh[1]);
                MMA_BF16(oacc[nf], ph, bl[0], bl[1]);
            }
        }
    }

    // epilogue: normalize, split, write g_att hi/lo
    const float inv0 = 1.0f / l0, inv1 = 1.0f / l1;
    const int row0 = qbase + wid * 16 + (lane >> 2);
    const size_t obase = (size_t)b * S_ * U_ + (size_t)row0 * U_ + h * DK_ + 2 * (lane & 3);
#pragma unroll
    for (int nf = 0; nf < 8; nf++) {
        uint32_t h32, l32;
        pack_split2(oacc[nf][0] * inv0, oacc[nf][1] * inv0, h32, l32);
        *(uint32_t*)(g_att_hi + obase + 8 * nf) = h32;
        *(uint32_t*)(g_att_lo + obase + 8 * nf) = l32;
        pack_split2(oacc[nf][2] * inv1, oacc[nf][3] * inv1, h32, l32);
        *(uint32_t*)(g_att_hi + obase + 8 * (size_t)U_ + 8 * nf) = h32;
        *(uint32_t*)(g_att_lo + obase + 8 * (size_t)U_ + 8 * nf) = l32;
    }
}

// ---------------------------------------------------------------------------
extern "C" void kernel_launch(void* const* d_in, const int* in_sizes, int n_in,
                              void* d_out, int out_size) {
    const float* query = (const float*)d_in[0];
    const float* key   = (const float*)d_in[1];
    const float* value = (const float*)d_in[2];
    const float* Wq = (const float*)d_in[4];
    const float* bq = (const float*)d_in[5];
    const float* Wk = (const float*)d_in[6];
    const float* bk = (const float*)d_in[7];
    const float* Wv = (const float*)d_in[8];
    const float* bv = (const float*)d_in[9];
    const float* Wo = (const float*)d_in[10];
    const float* bo = (const float*)d_in[11];
    float* out = (float*)d_out;

    cudaFuncSetAttribute(gemm_bf_qkv_b, cudaFuncAttributeMaxDynamicSharedMemorySize, G_SMEM);
    cudaFuncSetAttribute(gemm_bf_out, cudaFuncAttributeMaxDynamicSharedMemorySize, G_SMEM);
    cudaFuncSetAttribute(flash_attn_mma, cudaFuncAttributeMaxDynamicSharedMemorySize, ATT_SMEM);

    static __nv_bfloat16 *p_iqh = nullptr, *p_iql, *p_ikh, *p_ikl, *p_ivh, *p_ivl;
    static __nv_bfloat16 *p_wqh, *p_wql, *p_wkh, *p_wkl, *p_wvh, *p_wvl, *p_woh, *p_wol;
    if (!p_iqh) {
        cudaGetSymbolAddress((void**)&p_iqh, in_q_hi);
        cudaGetSymbolAddress((void**)&p_iql, in_q_lo);
        cudaGetSymbolAddress((void**)&p_ikh, in_k_hi);
        cudaGetSymbolAddress((void**)&p_ikl, in_k_lo);
        cudaGetSymbolAddress((void**)&p_ivh, in_v_hi);
        cudaGetSymbolAddress((void**)&p_ivl, in_v_lo);
        cudaGetSymbolAddress((void**)&p_wqh, w_q_hi);
        cudaGetSymbolAddress((void**)&p_wql, w_q_lo);
        cudaGetSymbolAddress((void**)&p_wkh, w_k_hi);
        cudaGetSymbolAddress((void**)&p_wkl, w_k_lo);
        cudaGetSymbolAddress((void**)&p_wvh, w_v_hi);
        cudaGetSymbolAddress((void**)&p_wvl, w_v_lo);
        cudaGetSymbolAddress((void**)&p_woh, w_o_hi);
        cudaGetSymbolAddress((void**)&p_wol, w_o_lo);
    }

    dim3 gc(1024, 7, 1);
    convert_all_kernel<<<gc, 256>>>(query, key, value, Wq, Wk, Wv, Wo,
                                    p_iqh, p_iql, p_ikh, p_ikl, p_ivh, p_ivl,
                                    p_wqh, p_wql, p_wkh, p_wkl, p_wvh, p_wvl,
                                    p_woh, p_wol);

    dim3 gq(U_ / 256, BS_ / 128, 3);
    gemm_bf_qkv_b<<<gq, 512, G_SMEM>>>(bq, bk, bv);

    dim3 ga(S_ / 128, H_, B_);
    flash_attn_mma<<<ga, 256, ATT_SMEM>>>();

    dim3 go(U_ / 256, BS_ / 128, 1);
    gemm_bf_out<<<go, 512, G_SMEM>>>(bo, out);
}

// round 14
// speedup vs baseline: 1.3454x; 1.0320x over previous
#include <cuda_runtime.h>
#include <cuda_bf16.h>
#include <cstdint>

#define B_  2
#define S_  2048
#define U_  1024
#define H_  16
#define DK_ 64
#define BS_ (B_ * S_)

// persistent split-bf16 scratch (allocation-free rule: __device__ globals)
__device__ __nv_bfloat16 in_q_hi[BS_ * U_], in_q_lo[BS_ * U_];
__device__ __nv_bfloat16 in_k_hi[BS_ * U_], in_k_lo[BS_ * U_];
__device__ __nv_bfloat16 in_v_hi[BS_ * U_], in_v_lo[BS_ * U_];
__device__ __nv_bfloat16 w_q_hi[U_ * U_], w_q_lo[U_ * U_];
__device__ __nv_bfloat16 w_k_hi[U_ * U_], w_k_lo[U_ * U_];
__device__ __nv_bfloat16 w_v_hi[U_ * U_], w_v_lo[U_ * U_];
__device__ __nv_bfloat16 w_o_hi[U_ * U_], w_o_lo[U_ * U_];
__device__ __nv_bfloat16 g_q_hi[BS_ * U_], g_q_lo[BS_ * U_];
__device__ __nv_bfloat16 g_k_hi[BS_ * U_], g_k_lo[BS_ * U_];
__device__ __nv_bfloat16 g_v_hi[BS_ * U_], g_v_lo[BS_ * U_];
__device__ __nv_bfloat16 g_att_hi[BS_ * U_], g_att_lo[BS_ * U_];

// ---------------------------------------------------------------------------
// helpers
// ---------------------------------------------------------------------------
__device__ __forceinline__ uint32_t smem_u32(const void* p) {
    uint32_t a;
    asm("{ .reg .u64 t; cvta.to.shared.u64 t, %1; cvt.u32.u64 %0, t; }" : "=r"(a) : "l"(p));
    return a;
}

#define LDSM_X4(r0, r1, r2, r3, addr)                                         \
    asm volatile("ldmatrix.sync.aligned.m8n8.x4.shared.b16 {%0,%1,%2,%3}, [%4];" \
        : "=r"(r0), "=r"(r1), "=r"(r2), "=r"(r3) : "r"(addr))

#define LDSM_X4_T(r0, r1, r2, r3, addr)                                       \
    asm volatile("ldmatrix.sync.aligned.m8n8.x4.trans.shared.b16 {%0,%1,%2,%3}, [%4];" \
        : "=r"(r0), "=r"(r1), "=r"(r2), "=r"(r3) : "r"(addr))

#define MMA_BF16(d, a, b0, b1)                                                \
    asm volatile("mma.sync.aligned.m16n8k16.row.col.f32.bf16.bf16.f32 "       \
        "{%0,%1,%2,%3},{%4,%5,%6,%7},{%8,%9},{%0,%1,%2,%3};"                  \
        : "+f"((d)[0]), "+f"((d)[1]), "+f"((d)[2]), "+f"((d)[3])              \
        : "r"((a)[0]), "r"((a)[1]), "r"((a)[2]), "r"((a)[3]), "r"(b0), "r"(b1))

#define CP_ASYNC16(saddr, gptr) \
    asm volatile("cp.async.cg.shared.global [%0], [%1], 16;" :: "r"(saddr), "l"(gptr) : "memory")

// mbarrier primitives (base ISA)
#define MBARRIER_INIT(addr, cnt) \
    asm volatile("mbarrier.init.shared.b64 [%0], %1;" :: "r"(addr), "r"(cnt) : "memory")
#define MBARRIER_ARRIVE(addr) do { unsigned long long _t;                      \
    asm volatile("mbarrier.arrive.shared.b64 %0, [%1];" : "=l"(_t) : "r"(addr) : "memory"); } while (0)
// .noinc is load-bearing: pending count NOT incremented (round-11 deadlock fix)
#define CP_MBAR_ARRIVE(addr) \
    asm volatile("cp.async.mbarrier.arrive.noinc.shared.b64 [%0];" :: "r"(addr) : "memory")
#define MBARRIER_WAIT_PARITY(addr, par) do {                                  \
    uint32_t _m = (addr); uint32_t _p = (par); uint32_t _done;                \
    asm volatile("{ .reg .pred p; mbarrier.try_wait.parity.acquire.cta.shared::cta.b64 p, [%1], %2; selp.b32 %0,1,0,p; }" \
        : "=r"(_done) : "r"(_m), "r"(_p) : "memory");                         \
    if (!_done) {                                                             \
        asm volatile("{ .reg .pred P1; WAIT_LOOP_%=: mbarrier.try_wait.parity.acquire.cta.shared::cta.b64 P1, [%0], %1, 0x989680; @P1 bra.uni WAIT_DONE_%=; bra.uni WAIT_LOOP_%=; WAIT_DONE_%=: }" \
            :: "r"(_m), "r"(_p) : "memory");                                  \
    } } while (0)

__device__ __forceinline__ uint32_t pack_bf16(__nv_bfloat16 a, __nv_bfloat16 b) {
    uint32_t ua = *reinterpret_cast<unsigned short*>(&a);
    uint32_t ub = *reinterpret_cast<unsigned short*>(&b);
    return ua | (ub << 16);
}

__device__ __forceinline__ void cvt_split(const float4& f, uint2& hi, uint2& lo) {
    __nv_bfloat16 h0 = __float2bfloat16(f.x);
    __nv_bfloat16 h1 = __float2bfloat16(f.y);
    __nv_bfloat16 h2 = __float2bfloat16(f.z);
    __nv_bfloat16 h3 = __float2bfloat16(f.w);
    __nv_bfloat16 l0 = __float2bfloat16(f.x - __bfloat162float(h0));
    __nv_bfloat16 l1 = __float2bfloat16(f.y - __bfloat162float(h1));
    __nv_bfloat16 l2 = __float2bfloat16(f.z - __bfloat162float(h2));
    __nv_bfloat16 l3 = __float2bfloat16(f.w - __bfloat162float(h3));
    hi.x = pack_bf16(h0, h1); hi.y = pack_bf16(h2, h3);
    lo.x = pack_bf16(l0, l1); lo.y = pack_bf16(l2, l3);
}

__device__ __forceinline__ void pack_split2(float a, float b, uint32_t& hi, uint32_t& lo) {
    __nv_bfloat16 ha = __float2bfloat16(a), hb = __float2bfloat16(b);
    __nv_bfloat16 la = __float2bfloat16(a - __bfloat162float(ha));
    __nv_bfloat16 lb = __float2bfloat16(b - __bfloat162float(hb));
    hi = pack_bf16(ha, hb); lo = pack_bf16(la, lb);
}

// ---------------------------------------------------------------------------
// one-shot pre-pass: all 7 fp32 arrays -> (hi, lo) bf16.  blockIdx.y selects.
// ---------------------------------------------------------------------------
__global__ __launch_bounds__(256) void convert_all_kernel(
    const float* __restrict__ q, const float* __restrict__ k,
    const float* __restrict__ v, const float* __restrict__ wq,
    const float* __restrict__ wk, const float* __restrict__ wv,
    const float* __restrict__ wo,
    __nv_bfloat16* __restrict__ qh, __nv_bfloat16* __restrict__ ql,
    __nv_bfloat16* __restrict__ kh, __nv_bfloat16* __restrict__ kl,
    __nv_bfloat16* __restrict__ vh, __nv_bfloat16* __restrict__ vl,
    __nv_bfloat16* __restrict__ wqh, __nv_bfloat16* __restrict__ wql,
    __nv_bfloat16* __restrict__ wkh, __nv_bfloat16* __restrict__ wkl,
    __nv_bfloat16* __restrict__ wvh, __nv_bfloat16* __restrict__ wvl,
    __nv_bfloat16* __restrict__ woh, __nv_bfloat16* __restrict__ wol) {
    const float* src; __nv_bfloat16* hi; __nv_bfloat16* lo; int n4;
    switch (blockIdx.y) {
        case 0: src = q;  hi = qh;  lo = ql;  n4 = (BS_ * U_) / 4; break;
        case 1: src = k;  hi = kh;  lo = kl;  n4 = (BS_ * U_) / 4; break;
        case 2: src = v;  hi = vh;  lo = vl;  n4 = (BS_ * U_) / 4; break;
        case 3: src = wq; hi = wqh; lo = wql; n4 = (U_ * U_) / 4; break;
        case 4: src = wk; hi = wkh; lo = wkl; n4 = (U_ * U_) / 4; break;
        case 5: src = wv; hi = wvh; lo = wvl; n4 = (U_ * U_) / 4; break;
        default: src = wo; hi = woh; lo = wol; n4 = (U_ * U_) / 4; break;
    }
    for (int i = blockIdx.x * 256 + threadIdx.x; i < n4; i += 1024 * 256) {
        float4 f = ((const float4*)src)[i];
        uint2 h, l;
        cvt_split(f, h, l);
        ((uint2*)hi)[i] = h;
        ((uint2*)lo)[i] = l;
    }
}

// ---------------------------------------------------------------------------
// split-bf16 GEMM, 3-stage cp.async mbarrier pipeline (round-12, unchanged).
// ---------------------------------------------------------------------------
#define ROWB     80
#define ST_ALO   10240u
#define ST_WHI   20480u
#define ST_WLO   40960u
#define STAGE_B  61440
#define G_SMEM   (3 * STAGE_B)
#define NKC      (U_ / 32)

__device__ __forceinline__ void g_issue(uint32_t st,
                                        const __nv_bfloat16* __restrict__ Ah,
                                        const __nv_bfloat16* __restrict__ Al,
                                        const __nv_bfloat16* __restrict__ Wh,
                                        const __nv_bfloat16* __restrict__ Wl,
                                        int bm, int bn, int k0, int tid) {
    const int row = tid >> 2, seg = tid & 3;
    const uint32_t so = (uint32_t)(row * ROWB + seg * 16);
    const size_t ga  = (size_t)(bm + row) * U_ + k0 + seg * 8;
    const size_t gw0 = (size_t)(bn + row) * U_ + k0 + seg * 8;
    const size_t gw1 = (size_t)(bn + 128 + row) * U_ + k0 + seg * 8;
    CP_ASYNC16(st + so,                    Ah + ga);
    CP_ASYNC16(st + ST_ALO + so,           Al + ga);
    CP_ASYNC16(st + ST_WHI + so,           Wh + gw0);
    CP_ASYNC16(st + ST_WHI + 10240u + so,  Wh + gw1);
    CP_ASYNC16(st + ST_WLO + so,           Wl + gw0);
    CP_ASYNC16(st + ST_WLO + 10240u + so,  Wl + gw1);
}

template <bool SPLIT_OUT>
__device__ void gemm_bf_body(const __nv_bfloat16* __restrict__ Ah,
                             const __nv_bfloat16* __restrict__ Al,
                             const __nv_bfloat16* __restrict__ Wh,
                             const __nv_bfloat16* __restrict__ Wl,
                             const float* __restrict__ bias, float scale,
                             float* __restrict__ Cf,
                             __nv_bfloat16* __restrict__ Ch,
                             __nv_bfloat16* __restrict__ Cl) {
    extern __shared__ char smem[];
    __shared__ __align__(8) uint64_t s_mbar[6];   // full[0..2], empty[0..2]
    const int tid  = threadIdx.x;
    const int lane = tid & 31;
    const int wid  = tid >> 5;
    const int wm   = wid >> 2;
    const int wn   = wid & 3;
    const int bm   = blockIdx.y * 128;
    const int bn   = blockIdx.x * 256;
    const uint32_t sbase = smem_u32(smem);
    const uint32_t mb    = smem_u32(s_mbar);

    if (tid == 0) {
#pragma unroll
        for (int s = 0; s < 3; s++) {
            MBARRIER_INIT(mb + 8u * s, 512u);        // full
            MBARRIER_INIT(mb + 24u + 8u * s, 16u);   // empty
        }
    }
    __syncthreads();

    float acc[2][8][4];
#pragma unroll
    for (int mf = 0; mf < 2; mf++)
#pragma unroll
        for (int nf = 0; nf < 8; nf++)
#pragma unroll
            for (int r = 0; r < 4; r++) acc[mf][nf][r] = 0.0f;

    const uint32_t a_row  = (uint32_t)(lane & 15);
    const uint32_t a_colh = (uint32_t)(((lane >> 4) & 1) * 16);
    const uint32_t b_nl   = (uint32_t)((lane & 7) + ((lane >> 4) & 1) * 8);
    const uint32_t b_ks   = (uint32_t)(((lane >> 3) & 1) * 16);

    g_issue(sbase, Ah, Al, Wh, Wl, bm, bn, 0, tid);
    CP_MBAR_ARRIVE(mb + 0u);
    g_issue(sbase + STAGE_B, Ah, Al, Wh, Wl, bm, bn, 32, tid);
    CP_MBAR_ARRIVE(mb + 8u);

    for (int c = 0; c < NKC; c++) {
        const int s = c % 3;
        MBARRIER_WAIT_PARITY(mb + 8u * (uint32_t)s, (uint32_t)((c / 3) & 1));

        const uint32_t st = sbase + (uint32_t)s * STAGE_B;
#pragma unroll
        for (int ko = 0; ko < 2; ko++) {
            uint32_t ah[2][4], al[2][4];
#pragma unroll
            for (int mf = 0; mf < 2; mf++) {
                uint32_t ad = st + (uint32_t)((wm * 32 + mf * 16 + a_row) * ROWB)
                                 + (uint32_t)(ko * 32) + a_colh;
                LDSM_X4(ah[mf][0], ah[mf][1], ah[mf][2], ah[mf][3], ad);
                LDSM_X4(al[mf][0], al[mf][1], al[mf][2], al[mf][3], ad + ST_ALO);
            }
            uint32_t bh[4][4], bl[4][4];
#pragma unroll
            for (int np = 0; np < 4; np++) {
                uint32_t bd = st + ST_WHI
                            + (uint32_t)((wn * 64 + np * 16 + b_nl) * ROWB)
                            + (uint32_t)(ko * 32) + b_ks;
                LDSM_X4(bh[np][0], bh[np][1], bh[np][2], bh[np][3], bd);
                LDSM_X4(bl[np][0], bl[np][1], bl[np][2], bl[np][3], bd + 20480u);
            }
#pragma unroll
            for (int mf = 0; mf < 2; mf++)
#pragma unroll
                for (int nf = 0; nf < 8; nf++) {
                    const uint32_t* bhp = &bh[nf >> 1][(nf & 1) * 2];
                    const uint32_t* blp = &bl[nf >> 1][(nf & 1) * 2];
                    MMA_BF16(acc[mf][nf], ah[mf], bhp[0], bhp[1]);
                    MMA_BF16(acc[mf][nf], ah[mf], blp[0], blp[1]);
                    MMA_BF16(acc[mf][nf], al[mf], bhp[0], bhp[1]);
                }
        }
        if (lane == 0) MBARRIER_ARRIVE(mb + 24u + 8u * (uint32_t)s);

        if (c + 2 < NKC) {
            const int n = c + 2, sn = n % 3;
            if (n >= 3)
                MBARRIER_WAIT_PARITY(mb + 24u + 8u * (uint32_t)sn,
                                     (uint32_t)(((n / 3) - 1) & 1));
            g_issue(sbase + (uint32_t)sn * STAGE_B, Ah, Al, Wh, Wl,
                    bm, bn, n * 32, tid);
            CP_MBAR_ARRIVE(mb + 8u * (uint32_t)sn);
        }
    }

    const int tr = lane >> 2;
    const int tc = (lane & 3) * 2;
#pragma unroll
    for (int mf = 0; mf < 2; mf++) {
#pragma unroll
        for (int nf = 0; nf < 8; nf++) {
            int gr = bm + wm * 32 + mf * 16 + tr;
            int gc = bn + wn * 64 + nf * 8 + tc;
            float2 bv = *(const float2*)(bias + gc);
            if (SPLIT_OUT) {
                float a0 = (acc[mf][nf][0] + bv.x) * scale;
                float a1 = (acc[mf][nf][1] + bv.y) * scale;
                float a2 = (acc[mf][nf][2] + bv.x) * scale;
                float a3 = (acc[mf][nf][3] + bv.y) * scale;
                uint32_t h, l;
                pack_split2(a0, a1, h, l);
                *(uint32_t*)(Ch + (size_t)gr * U_ + gc) = h;
                *(uint32_t*)(Cl + (size_t)gr * U_ + gc) = l;
                pack_split2(a2, a3, h, l);
                *(uint32_t*)(Ch + (size_t)(gr + 8) * U_ + gc) = h;
                *(uint32_t*)(Cl + (size_t)(gr + 8) * U_ + gc) = l;
            } else {
                float2 o0 = make_float2(acc[mf][nf][0] + bv.x, acc[mf][nf][1] + bv.y);
                float2 o1 = make_float2(acc[mf][nf][2] + bv.x, acc[mf][nf][3] + bv.y);
                *(float2*)(Cf + (size_t)gr * U_ + gc)       = o0;
                *(float2*)(Cf + (size_t)(gr + 8) * U_ + gc) = o1;
            }
        }
    }
}

__global__ __launch_bounds__(512, 1) void gemm_bf_qkv_b(
    const float* __restrict__ bq, const float* __restrict__ bk,
    const float* __restrict__ bv) {
    if (blockIdx.z == 0)
        gemm_bf_body<true>(in_q_hi, in_q_lo, w_q_hi, w_q_lo, bq, 0.125f,
                           nullptr, g_q_hi, g_q_lo);
    else if (blockIdx.z == 1)
        gemm_bf_body<true>(in_k_hi, in_k_lo, w_k_hi, w_k_lo, bk, 1.0f,
                           nullptr, g_k_hi, g_k_lo);
    else
        gemm_bf_body<true>(in_v_hi, in_v_lo, w_v_hi, w_v_lo, bv, 1.0f,
                           nullptr, g_v_hi, g_v_lo);
}

__global__ __launch_bounds__(512, 1) void gemm_bf_out(const float* __restrict__ bo,
                                                      float* __restrict__ out) {
    gemm_bf_body<false>(g_att_hi, g_att_lo, w_o_hi, w_o_lo, bo, 1.0f,
                        out, nullptr, nullptr);
}

// ---------------------------------------------------------------------------
// Flash attention, split-bf16 mma.sync, kv double-buffer driven by
// full/empty mbarriers (no per-tile __syncthreads / wait_group drain).
// smem: Qhi@0, Qlo@18432; stages @36864 + (jt&1)*36864:
//       Khi@0, Klo@9216, Vhi@18432, Vlo@27648 (row stride 144B)
// full[s]: count=256 (cp.async.mbarrier.arrive.noinc, all threads)
// empty[s]: count=8 (lane0 per warp after PV consumes the stage)
// ---------------------------------------------------------------------------
#define AROWB    144
#define AQ_LO_O  18432u
#define AST0     36864u
#define ASTAGE_B 36864u
#define ATT_SMEM 110592

__device__ __forceinline__ void kv_issue(uint32_t buf,
                                         const __nv_bfloat16* __restrict__ Kh,
                                         const __nv_bfloat16* __restrict__ Kl,
                                         const __nv_bfloat16* __restrict__ Vh,
                                         const __nv_bfloat16* __restrict__ Vl,
                                         int kbase, int tid) {
#pragma unroll
    for (int i = 0; i < 2; i++) {
        int id  = tid * 2 + i;
        int row = id >> 3, seg = id & 7;
        uint32_t so = (uint32_t)(row * AROWB + seg * 16);
        size_t go = (size_t)(kbase + row) * U_ + seg * 8;
        CP_ASYNC16(buf + so,          Kh + go);
        CP_ASYNC16(buf + 9216u + so,  Kl + go);
        CP_ASYNC16(buf + 18432u + so, Vh + go);
        CP_ASYNC16(buf + 27648u + so, Vl + go);
    }
}

__global__ __launch_bounds__(256, 1) void flash_attn_mma() {
    extern __shared__ char smem[];
    __shared__ __align__(8) uint64_t a_mbar[4];   // full[0..1], empty[0..1]
    const uint32_t sb = smem_u32(smem);
    const uint32_t mb = smem_u32(a_mbar);
    const int tid  = threadIdx.x;
    const int lane = tid & 31;
    const int wid  = tid >> 5;
    const int qt   = (int)gridDim.x - 1 - (int)blockIdx.x;   // big tiles first
    const int h    = blockIdx.y;
    const int b    = blockIdx.z;
    const int qbase = qt * 128;

    if (tid == 0) {
        MBARRIER_INIT(mb + 0u,  256u);   // full[0]
        MBARRIER_INIT(mb + 8u,  256u);   // full[1]
        MBARRIER_INIT(mb + 16u, 8u);     // empty[0]
        MBARRIER_INIT(mb + 24u, 8u);     // empty[1]
    }
    __syncthreads();

    const size_t head_off = (size_t)b * S_ * U_ + h * DK_;
    const __nv_bfloat16* Qh = g_q_hi + head_off + (size_t)qbase * U_;
    const __nv_bfloat16* Ql = g_q_lo + head_off + (size_t)qbase * U_;
    const __nv_bfloat16* Kh = g_k_hi + head_off;
    const __nv_bfloat16* Kl = g_k_lo + head_off;
    const __nv_bfloat16* Vh = g_v_hi + head_off;
    const __nv_bfloat16* Vl = g_v_lo + head_off;

    // Q tile + kv0 -> full[0] (arrive tracks both); kv1 -> full[1]
#pragma unroll
    for (int i = 0; i < 4; i++) {
        int id  = tid * 4 + i;
        int row = id >> 3, seg = id & 7;
        uint32_t so = (uint32_t)(row * AROWB + seg * 16);
        size_t go = (size_t)row * U_ + seg * 8;
        CP_ASYNC16(sb + so,           Qh + go);
        CP_ASYNC16(sb + AQ_LO_O + so, Ql + go);
    }
    kv_issue(sb + AST0, Kh, Kl, Vh, Vl, 0, tid);
    CP_MBAR_ARRIVE(mb + 0u);
    kv_issue(sb + AST0 + ASTAGE_B, Kh, Kl, Vh, Vl, 64, tid);  // njt >= 2 always
    CP_MBAR_ARRIVE(mb + 8u);

    const uint32_t a_row  = (uint32_t)(lane & 15);
    const uint32_t a_colh = (uint32_t)(((lane >> 4) & 1) * 16);
    const uint32_t b_nl   = (uint32_t)((lane & 7) + ((lane >> 4) & 1) * 8);
    const uint32_t b_ks   = (uint32_t)(((lane >> 3) & 1) * 16);
    const uint32_t v_row  = (uint32_t)(((lane >> 3) & 1) * 8 + (lane & 7));
    const uint32_t v_colh = (uint32_t)(((lane >> 4) & 1) * 16);

    // hoist Q fragments: full[0] covers Q (non-consuming parity wait, acquire)
    MBARRIER_WAIT_PARITY(mb + 0u, 0u);
    uint32_t qh[4][4], ql[4][4];
#pragma unroll
    for (int ko = 0; ko < 4; ko++) {
        uint32_t ad = sb + (uint32_t)((wid * 16 + a_row) * AROWB)
                    + (uint32_t)(ko * 32) + a_colh;
        LDSM_X4(qh[ko][0], qh[ko][1], qh[ko][2], qh[ko][3], ad);
        LDSM_X4(ql[ko][0], ql[ko][1], ql[ko][2], ql[ko][3], ad + AQ_LO_O);
    }

    float m0 = -1e30f, m1 = -1e30f, l0 = 0.0f, l1 = 0.0f;
    float oacc[8][4];
#pragma unroll
    for (int nf = 0; nf < 8; nf++)
#pragma unroll
        for (int r = 0; r < 4; r++) oacc[nf][r] = 0.0f;

    const int njt = 2 * qt + 2;
    for (int jt = 0; jt < njt; jt++) {
        const int kbase = jt * 64;
        const int s = jt & 1;
        const uint32_t use = (uint32_t)(jt >> 1);
        MBARRIER_WAIT_PARITY(mb + 8u * (uint32_t)s, use & 1u);

        const uint32_t st = sb + AST0 + (uint32_t)s * ASTAGE_B;

        // S = Q K^T
        float sacc[8][4];
#pragma unroll
        for (int j = 0; j < 8; j++)
#pragma unroll
            for (int r = 0; r < 4; r++) sacc[j][r] = 0.0f;

#pragma unroll
        for (int ko = 0; ko < 4; ko++) {
#pragma unroll
            for (int np = 0; np < 4; np++) {
                uint32_t kh[4], kl[4];
                uint32_t bd = st + (uint32_t)((np * 16 + b_nl) * AROWB)
                            + (uint32_t)(ko * 32) + b_ks;
                LDSM_X4(kh[0], kh[1], kh[2], kh[3], bd);
                LDSM_X4(kl[0], kl[1], kl[2], kl[3], bd + 9216u);
#pragma unroll
                for (int half = 0; half < 2; half++) {
                    float* d = sacc[2 * np + half];
                    const uint32_t* bh = &kh[half * 2];
                    const uint32_t* bl = &kl[half * 2];
                    MMA_BF16(d, qh[ko], bh[0], bh[1]);
                    MMA_BF16(d, qh[ko], bl[0], bl[1]);
                    MMA_BF16(d, ql[ko], bh[0], bh[1]);
                }
            }
        }

        // causal mask on diagonal-overlapping tiles
        if (jt >= 2 * qt) {
            const int row0 = qbase + wid * 16 + (lane >> 2);
            const int row1 = row0 + 8;
#pragma unroll
            for (int j = 0; j < 8; j++) {
                int col = kbase + 8 * j + 2 * (lane & 3);
                if (col > row0)     sacc[j][0] = -1e9f;
                if (col + 1 > row0) sacc[j][1] = -1e9f;
                if (col > row1)     sacc[j][2] = -1e9f;
                if (col + 1 > row1) sacc[j][3] = -1e9f;
            }
        }

        // online softmax (in-warp quad reductions)
        float rm0 = -1e30f, rm1 = -1e30f;
#pragma unroll
        for (int j = 0; j < 8; j++) {
            rm0 = fmaxf(rm0, fmaxf(sacc[j][0], sacc[j][1]));
            rm1 = fmaxf(rm1, fmaxf(sacc[j][2], sacc[j][3]));
        }
        rm0 = fmaxf(rm0, __shfl_xor_sync(0xffffffffu, rm0, 1));
        rm0 = fmaxf(rm0, __shfl_xor_sync(0xffffffffu, rm0, 2));
        rm1 = fmaxf(rm1, __shfl_xor_sync(0xffffffffu, rm1, 1));
        rm1 = fmaxf(rm1, __shfl_xor_sync(0xffffffffu, rm1, 2));
        float mn0 = fmaxf(m0, rm0), mn1 = fmaxf(m1, rm1);
        float corr0 = __expf(m0 - mn0), corr1 = __expf(m1 - mn1);
        m0 = mn0; m1 = mn1;
        float rs0 = 0.0f, rs1 = 0.0f;
#pragma unroll
        for (int j = 0; j < 8; j++) {
            float p0 = __expf(sacc[j][0] - mn0);
            float p1 = __expf(sacc[j][1] - mn0);
            float p2 = __expf(sacc[j][2] - mn1);
            float p3 = __expf(sacc[j][3] - mn1);
            sacc[j][0] = p0; sacc[j][1] = p1; sacc[j][2] = p2; sacc[j][3] = p3;
            rs0 += p0 + p1; rs1 += p2 + p3;
        }
        rs0 += __shfl_xor_sync(0xffffffffu, rs0, 1);
        rs0 += __shfl_xor_sync(0xffffffffu, rs0, 2);
        rs1 += __shfl_xor_sync(0xffffffffu, rs1, 1);
        rs1 += __shfl_xor_sync(0xffffffffu, rs1, 2);
        l0 = l0 * corr0 + rs0;
        l1 = l1 * corr1 + rs1;
#pragma unroll
        for (int nf = 0; nf < 8; nf++) {
            oacc[nf][0] *= corr0; oacc[nf][1] *= corr0;
            oacc[nf][2] *= corr1; oacc[nf][3] *= corr1;
        }

        // O += P V
#pragma unroll
        for (int t = 0; t < 4; t++) {
            uint32_t ph[4], pl[4];
            pack_split2(sacc[2 * t][0],     sacc[2 * t][1],     ph[0], pl[0]);
            pack_split2(sacc[2 * t][2],     sacc[2 * t][3],     ph[1], pl[1]);
            pack_split2(sacc[2 * t + 1][0], sacc[2 * t + 1][1], ph[2], pl[2]);
            pack_split2(sacc[2 * t + 1][2], sacc[2 * t + 1][3], ph[3], pl[3]);
            uint32_t vh[4][4], vl[4][4];
#pragma unroll
            for (int g = 0; g < 4; g++) {
                uint32_t va = st + 18432u + (uint32_t)((t * 16 + v_row) * AROWB)
                            + v_colh + (uint32_t)(g * 32);
                LDSM_X4_T(vh[g][0], vh[g][1], vh[g][2], vh[g][3], va);
                LDSM_X4_T(vl[g][0], vl[g][1], vl[g][2], vl[g][3], va + 9216u);
            }
#pragma unroll
            for (int nf = 0; nf < 8; nf++) {
                const int g = nf >> 1;
                const uint32_t* bh = &vh[g][(nf & 1) * 2];
                const uint32_t* bl = &vl[g][(nf & 1) * 2];
                MMA_BF16(oacc[nf], ph, bh[0], bh[1]);
                MMA_BF16(oacc[nf], pl, bh[0], bh[1]);
                MMA_BF16(oacc[nf], ph, bl[0], bl[1]);
            }
        }

        // this warp is done reading stage s
        if (lane == 0) MBARRIER_ARRIVE(mb + 16u + 8u * (uint32_t)s);

        if (jt + 2 < njt) {
            // wait all 8 warps done with stage s (completion index = use)
            MBARRIER_WAIT_PARITY(mb + 16u + 8u * (uint32_t)s, use & 1u);
            kv_issue(st, Kh, Kl, Vh, Vl, (jt + 2) * 64, tid);
            CP_MBAR_ARRIVE(mb + 8u * (uint32_t)s);
        }
    }

    // epilogue: normalize, split, write g_att hi/lo
    const float inv0 = 1.0f / l0, inv1 = 1.0f / l1;
    const int row0 = qbase + wid * 16 + (lane >> 2);
    const size_t obase = (size_t)b * S_ * U_ + (size_t)row0 * U_ + h * DK_ + 2 * (lane & 3);
#pragma unroll
    for (int nf = 0; nf < 8; nf++) {
        uint32_t h32, l32;
        pack_split2(oacc[nf][0] * inv0, oacc[nf][1] * inv0, h32, l32);
        *(uint32_t*)(g_att_hi + obase + 8 * nf) = h32;
        *(uint32_t*)(g_att_lo + obase + 8 * nf) = l32;
        pack_split2(oacc[nf][2] * inv1, oacc[nf][3] * inv1, h32, l32);
        *(uint32_t*)(g_att_hi + obase + 8 * (size_t)U_ + 8 * nf) = h32;
        *(uint32_t*)(g_att_lo + obase + 8 * (size_t)U_ + 8 * nf) = l32;
    }
}

// ---------------------------------------------------------------------------
extern "C" void kernel_launch(void* const* d_in, const int* in_sizes, int n_in,
                              void* d_out, int out_size) {
    const float* query = (const float*)d_in[0];
    const float* key   = (const float*)d_in[1];
    const float* value = (const float*)d_in[2];
    const float* Wq = (const float*)d_in[4];
    const float* bq = (const float*)d_in[5];
    const float* Wk = (const float*)d_in[6];
    const float* bk = (const float*)d_in[7];
    const float* Wv = (const float*)d_in[8];
    const float* bv = (const float*)d_in[9];
    const float* Wo = (const float*)d_in[10];
    const float* bo = (const float*)d_in[11];
    float* out = (float*)d_out;

    cudaFuncSetAttribute(gemm_bf_qkv_b, cudaFuncAttributeMaxDynamicSharedMemorySize, G_SMEM);
    cudaFuncSetAttribute(gemm_bf_out, cudaFuncAttributeMaxDynamicSharedMemorySize, G_SMEM);
    cudaFuncSetAttribute(flash_attn_mma, cudaFuncAttributeMaxDynamicSharedMemorySize, ATT_SMEM);

    static __nv_bfloat16 *p_iqh = nullptr, *p_iql, *p_ikh, *p_ikl, *p_ivh, *p_ivl;
    static __nv_bfloat16 *p_wqh, *p_wql, *p_wkh, *p_wkl, *p_wvh, *p_wvl, *p_woh, *p_wol;
    if (!p_iqh) {
        cudaGetSymbolAddress((void**)&p_iqh, in_q_hi);
        cudaGetSymbolAddress((void**)&p_iql, in_q_lo);
        cudaGetSymbolAddress((void**)&p_ikh, in_k_hi);
        cudaGetSymbolAddress((void**)&p_ikl, in_k_lo);
        cudaGetSymbolAddress((void**)&p_ivh, in_v_hi);
        cudaGetSymbolAddress((void**)&p_ivl, in_v_lo);
        cudaGetSymbolAddress((void**)&p_wqh, w_q_hi);
        cudaGetSymbolAddress((void**)&p_wql, w_q_lo);
        cudaGetSymbolAddress((void**)&p_wkh, w_k_hi);
        cudaGetSymbolAddress((void**)&p_wkl, w_k_lo);
        cudaGetSymbolAddress((void**)&p_wvh, w_v_hi);
        cudaGetSymbolAddress((void**)&p_wvl, w_v_lo);
        cudaGetSymbolAddress((void**)&p_woh, w_o_hi);
        cudaGetSymbolAddress((void**)&p_wol, w_o_lo);
    }

    dim3 gc(1024, 7, 1);
    convert_all_kernel<<<gc, 256>>>(query, key, value, Wq, Wk, Wv, Wo,
                                    p_iqh, p_iql, p_ikh, p_ikl, p_ivh, p_ivl,
                                    p_wqh, p_wql, p_wkh, p_wkl, p_wvh, p_wvl,
                                    p_woh, p_wol);

    dim3 gq(U_ / 256, BS_ / 128, 3);
    gemm_bf_qkv_b<<<gq, 512, G_SMEM>>>(bq, bk, bv);

    dim3 ga(S_ / 128, H_, B_);
    flash_attn_mma<<<ga, 256, ATT_SMEM>>>();

    dim3 go(U_ / 256, BS_ / 128, 1);
    gemm_bf_out<<<go, 512, G_SMEM>>>(bo, out);
}